// round 14
// baseline (speedup 1.0000x reference)
#include <cuda_runtime.h>
#include <math.h>

#define NMAX 50000
#define EMAX 800000
#define D 128
#define NB_SCAN ((NMAX + 1023) / 1024)

// ---------------- scratch (device globals; no allocation allowed) ----------
__device__ int    g_is64;
__device__ int    g_degi[NMAX];
__device__ int    g_off[NMAX + 1];
__device__ int    g_cur[NMAX];
__device__ int    g_bsum[NB_SCAN];
__device__ int    g_bpre[NB_SCAN];
__device__ float  g_dinv[NMAX];
__device__ float2 g_emeta[EMAX];   // {src (bitcast int), norm}
__device__ float  g_ha[NMAX * D];
__device__ float  g_hb[NMAX * D];
__device__ float  g_x[NMAX * D];

// ---------------- f32x2 helpers (Blackwell packed fp32) ---------------------
__device__ __forceinline__ unsigned long long pk2(float lo, float hi) {
    unsigned long long d;
    asm("mov.b64 %0, {%1, %2};" : "=l"(d) : "f"(lo), "f"(hi));
    return d;
}
__device__ __forceinline__ float2 upk2(unsigned long long v) {
    float2 r;
    asm("mov.b64 {%0, %1}, %2;" : "=f"(r.x), "=f"(r.y) : "l"(v));
    return r;
}
__device__ __forceinline__ unsigned long long fma2(unsigned long long a,
                                                   unsigned long long b,
                                                   unsigned long long c) {
    unsigned long long d;
    asm("fma.rn.f32x2 %0, %1, %2, %3;" : "=l"(d) : "l"(a), "l"(b), "l"(c));
    return d;
}

__device__ __forceinline__ float leaky1(float v) {
    return v >= 0.0f ? v : 0.01f * v;
}

// ---------------- edge-index width detection -------------------------------
__global__ void detect_k(const unsigned int* __restrict__ w, int E) {
    __shared__ int nz;
    if (threadIdx.x == 0) nz = 0;
    __syncthreads();
    int n = E < 1024 ? E : 1024;
    for (int i = threadIdx.x; i < n; i += 32)
        if (w[2 * i + 1] != 0u) atomicAdd(&nz, 1);
    __syncthreads();
    if (threadIdx.x == 0) g_is64 = (nz == 0) ? 1 : 0;
}

// ---------------- degree histogram ------------------------------------------
__global__ void count_k(const void* __restrict__ ei, int E) {
    int e = blockIdx.x * blockDim.x + threadIdx.x;
    if (e >= E) return;
    int dst;
    if (g_is64) dst = (int)((const unsigned int*)ei)[2 * (E + e)];
    else        dst = ((const int*)ei)[E + e];
    atomicAdd(&g_degi[dst], 1);
}

// ---------------- scan phase 1 (+ dinv fused) --------------------------------
__global__ void scan1_k(int N) {
    __shared__ int sh[1024];
    int t = threadIdx.x;
    int i = blockIdx.x * 1024 + t;
    int v = (i < N) ? g_degi[i] : 0;
    if (i < N) g_dinv[i] = rsqrtf((float)v + 1.0f);  // + self loop
    sh[t] = v;
    __syncthreads();
#pragma unroll
    for (int off = 1; off < 1024; off <<= 1) {
        int u = (t >= off) ? sh[t - off] : 0;
        __syncthreads();
        sh[t] += u;
        __syncthreads();
    }
    if (i < N) g_off[i] = sh[t] - v;            // block-local exclusive
    if (t == 1023) g_bsum[blockIdx.x] = sh[1023];
}

// 64-thread Hillis-Steele over <=64 block sums
__global__ void scan2_k(int nb) {
    __shared__ int sh[64];
    int t = threadIdx.x;
    int v = (t < nb) ? g_bsum[t] : 0;
    sh[t] = v;
    __syncthreads();
#pragma unroll
    for (int off = 1; off < 64; off <<= 1) {
        int u = (t >= off) ? sh[t - off] : 0;
        __syncthreads();
        sh[t] += u;
        __syncthreads();
    }
    if (t < nb) g_bpre[t] = sh[t] - v;          // exclusive
}

__global__ void scan3_k(int N, int E) {
    int i = blockIdx.x * blockDim.x + threadIdx.x;
    if (i < N) {
        int v = g_off[i] + g_bpre[i >> 10];
        g_off[i] = v;
        g_cur[i] = v;
    }
    if (i == 0) g_off[N] = E;   // sum of degrees == E
}

// ---------------- CSR fill: bucket edges by dst -----------------------------
__global__ void fill_k(const void* __restrict__ ei, int E) {
    int e = blockIdx.x * blockDim.x + threadIdx.x;
    if (e >= E) return;
    int src, dst;
    if (g_is64) {
        src = (int)((const unsigned int*)ei)[2 * e];
        dst = (int)((const unsigned int*)ei)[2 * (E + e)];
    } else {
        src = ((const int*)ei)[e];
        dst = ((const int*)ei)[E + e];
    }
    float norm = g_dinv[src] * g_dinv[dst];
    int p = atomicAdd(&g_cur[dst], 1);
    g_emeta[p] = make_float2(__int_as_float(src), norm);
}

// ---------------- GEMM: H = X @ W  (K=128, NOUT=128), rows [rowBase,rowEnd) -
__global__ void gemm128_k(const float* __restrict__ X,
                          const float* __restrict__ W,
                          float* __restrict__ H, int rowBase, int rowEnd) {
    extern __shared__ float4 Ws4[];  // D*128 floats
    const float4* W4 = (const float4*)W;
    for (int i = threadIdx.x; i < D * 128 / 4; i += blockDim.x) Ws4[i] = W4[i];
    __syncthreads();

    constexpr int P = 4;  // row pairs (8 rows per warp)
    int lane = threadIdx.x & 31;
    int warp_g = blockIdx.x * (blockDim.x >> 5) + (threadIdx.x >> 5);
    int row0 = rowBase + warp_g * 8;
    if (row0 >= rowEnd) return;

    unsigned long long xp[P][4];
#pragma unroll
    for (int p = 0; p < P; p++) {
        int r0 = row0 + 2 * p, r1 = r0 + 1;
        float4 a = (r0 < rowEnd) ? ((const float4*)(X + (size_t)r0 * D))[lane]
                                 : make_float4(0.f, 0.f, 0.f, 0.f);
        float4 b = (r1 < rowEnd) ? ((const float4*)(X + (size_t)r1 * D))[lane]
                                 : make_float4(0.f, 0.f, 0.f, 0.f);
        xp[p][0] = pk2(a.x, b.x);
        xp[p][1] = pk2(a.y, b.y);
        xp[p][2] = pk2(a.z, b.z);
        xp[p][3] = pk2(a.w, b.w);
    }

    unsigned long long acc[P][4];
#pragma unroll
    for (int p = 0; p < P; p++)
#pragma unroll
        for (int c = 0; c < 4; c++) acc[p][c] = 0ull;

    for (int sl = 0; sl < 32; ++sl) {
#pragma unroll
        for (int kl = 0; kl < 4; kl++) {
            unsigned long long xs[P];
#pragma unroll
            for (int p = 0; p < P; p++)
                xs[p] = __shfl_sync(0xffffffffu, xp[p][kl], sl);
            int k = sl * 4 + kl;
            float4 wv = Ws4[(size_t)k * 32 + lane];
            unsigned long long w0 = pk2(wv.x, wv.x);
            unsigned long long w1 = pk2(wv.y, wv.y);
            unsigned long long w2 = pk2(wv.z, wv.z);
            unsigned long long w3 = pk2(wv.w, wv.w);
#pragma unroll
            for (int p = 0; p < P; p++) {
                acc[p][0] = fma2(xs[p], w0, acc[p][0]);
                acc[p][1] = fma2(xs[p], w1, acc[p][1]);
                acc[p][2] = fma2(xs[p], w2, acc[p][2]);
                acc[p][3] = fma2(xs[p], w3, acc[p][3]);
            }
        }
    }

#pragma unroll
    for (int p = 0; p < P; p++) {
        int r0 = row0 + 2 * p, r1 = r0 + 1;
        float2 c0 = upk2(acc[p][0]);
        float2 c1 = upk2(acc[p][1]);
        float2 c2 = upk2(acc[p][2]);
        float2 c3 = upk2(acc[p][3]);
        if (r0 < rowEnd)
            ((float4*)(H + (size_t)r0 * 128))[lane] =
                make_float4(c0.x, c1.x, c2.x, c3.x);
        if (r1 < rowEnd)
            ((float4*)(H + (size_t)r1 * 128))[lane] =
                make_float4(c0.y, c1.y, c2.y, c3.y);
    }
}

// ------- gather rows [rowBase,rowEnd): X[i]=leaky(dinv^2*H[i]+sum norm*H[s])-
__global__ void gather_k(const float* __restrict__ H, float* __restrict__ X,
                         int rowBase, int rowEnd) {
    int lane = threadIdx.x & 31;
    int node = rowBase + blockIdx.x * (blockDim.x >> 5) + (threadIdx.x >> 5);
    if (node >= rowEnd) return;
    int beg = g_off[node], end = g_off[node + 1];
    float s = g_dinv[node];
    float w0 = s * s;
    float4 acc = ((const float4*)(H + (size_t)node * D))[lane];
    acc.x *= w0; acc.y *= w0; acc.z *= w0; acc.w *= w0;

    int j = beg;
    for (; j + 1 < end; j += 2) {
        float2 m0 = g_emeta[j];
        float2 m1 = g_emeta[j + 1];
        int s0 = __float_as_int(m0.x);
        int s1 = __float_as_int(m1.x);
        float4 v0 = ((const float4*)(H + (size_t)s0 * D))[lane];
        float4 v1 = ((const float4*)(H + (size_t)s1 * D))[lane];
        acc.x += m0.y * v0.x + m1.y * v1.x;
        acc.y += m0.y * v0.y + m1.y * v1.y;
        acc.z += m0.y * v0.z + m1.y * v1.z;
        acc.w += m0.y * v0.w + m1.y * v1.w;
    }
    if (j < end) {
        float2 m = g_emeta[j];
        int src = __float_as_int(m.x);
        float w = m.y;
        float4 v = ((const float4*)(H + (size_t)src * D))[lane];
        acc.x += w * v.x; acc.y += w * v.y;
        acc.z += w * v.z; acc.w += w * v.w;
    }
    acc.x = leaky1(acc.x); acc.y = leaky1(acc.y);
    acc.z = leaky1(acc.z); acc.w = leaky1(acc.w);
    ((float4*)(X + (size_t)node * D))[lane] = acc;
}

// ---------------- fused fc1 + leaky + fc2 + softmax, rows [rowBase,rowEnd) --
// Launch with 768 threads (24 warps, 4 rows/warp = 96 rows/block).
__global__ void __launch_bounds__(768, 1)
fc_fused_k(const float* __restrict__ X,
           const float* __restrict__ W1,
           const float* __restrict__ W2,
           float* __restrict__ out, int rowBase, int rowEnd) {
    extern __shared__ float4 Ws4[];  // D*256 floats for W1, then 512 for W2
    float4* W2s4 = Ws4 + D * 256 / 4;
    const float4* W14 = (const float4*)W1;
    for (int i = threadIdx.x; i < D * 256 / 4; i += blockDim.x) Ws4[i] = W14[i];
    float* W2s = (float*)W2s4;
    for (int i = threadIdx.x; i < 256; i += blockDim.x) {
        W2s[i]       = W2[2 * i];
        W2s[256 + i] = W2[2 * i + 1];
    }
    __syncthreads();

    constexpr int P = 2;  // row pairs (4 rows per warp)
    int lane = threadIdx.x & 31;
    int warp_g = blockIdx.x * (blockDim.x >> 5) + (threadIdx.x >> 5);
    int row0 = rowBase + warp_g * 4;
    if (row0 >= rowEnd) return;

    unsigned long long xp[P][4];
#pragma unroll
    for (int p = 0; p < P; p++) {
        int r0 = row0 + 2 * p, r1 = r0 + 1;
        float4 a = (r0 < rowEnd) ? ((const float4*)(X + (size_t)r0 * D))[lane]
                                 : make_float4(0.f, 0.f, 0.f, 0.f);
        float4 b = (r1 < rowEnd) ? ((const float4*)(X + (size_t)r1 * D))[lane]
                                 : make_float4(0.f, 0.f, 0.f, 0.f);
        xp[p][0] = pk2(a.x, b.x);
        xp[p][1] = pk2(a.y, b.y);
        xp[p][2] = pk2(a.z, b.z);
        xp[p][3] = pk2(a.w, b.w);
    }

    unsigned long long acc[P][8];
#pragma unroll
    for (int p = 0; p < P; p++)
#pragma unroll
        for (int c = 0; c < 8; c++) acc[p][c] = 0ull;

    for (int sl = 0; sl < 32; ++sl) {
#pragma unroll
        for (int kl = 0; kl < 4; kl++) {
            unsigned long long xs[P];
#pragma unroll
            for (int p = 0; p < P; p++)
                xs[p] = __shfl_sync(0xffffffffu, xp[p][kl], sl);
            int k = sl * 4 + kl;
#pragma unroll
            for (int c = 0; c < 2; c++) {
                float4 wv = Ws4[(size_t)k * 64 + lane + 32 * c];
                unsigned long long w0 = pk2(wv.x, wv.x);
                unsigned long long w1 = pk2(wv.y, wv.y);
                unsigned long long w2 = pk2(wv.z, wv.z);
                unsigned long long w3 = pk2(wv.w, wv.w);
#pragma unroll
                for (int p = 0; p < P; p++) {
                    acc[p][4 * c + 0] = fma2(xs[p], w0, acc[p][4 * c + 0]);
                    acc[p][4 * c + 1] = fma2(xs[p], w1, acc[p][4 * c + 1]);
                    acc[p][4 * c + 2] = fma2(xs[p], w2, acc[p][4 * c + 2]);
                    acc[p][4 * c + 3] = fma2(xs[p], w3, acc[p][4 * c + 3]);
                }
            }
        }
    }

    const float4* w0s4 = (const float4*)W2s;
    const float4* w1s4 = (const float4*)(W2s + 256);
#pragma unroll
    for (int p = 0; p < P; p++) {
        int r0 = row0 + 2 * p, r1 = r0 + 1;
        float a0r0 = 0.f, a1r0 = 0.f, a0r1 = 0.f, a1r1 = 0.f;
#pragma unroll
        for (int c = 0; c < 2; c++) {
            float2 c0 = upk2(acc[p][4 * c + 0]);
            float2 c1 = upk2(acc[p][4 * c + 1]);
            float2 c2 = upk2(acc[p][4 * c + 2]);
            float2 c3 = upk2(acc[p][4 * c + 3]);
            float4 y0 = make_float4(leaky1(c0.x), leaky1(c1.x),
                                    leaky1(c2.x), leaky1(c3.x));
            float4 y1 = make_float4(leaky1(c0.y), leaky1(c1.y),
                                    leaky1(c2.y), leaky1(c3.y));
            float4 u0 = w0s4[lane + 32 * c];
            float4 u1 = w1s4[lane + 32 * c];
            a0r0 += y0.x * u0.x + y0.y * u0.y + y0.z * u0.z + y0.w * u0.w;
            a1r0 += y0.x * u1.x + y0.y * u1.y + y0.z * u1.z + y0.w * u1.w;
            a0r1 += y1.x * u0.x + y1.y * u0.y + y1.z * u0.z + y1.w * u0.w;
            a1r1 += y1.x * u1.x + y1.y * u1.y + y1.z * u1.z + y1.w * u1.w;
        }
#pragma unroll
        for (int o = 16; o; o >>= 1) {
            a0r0 += __shfl_xor_sync(0xffffffffu, a0r0, o);
            a1r0 += __shfl_xor_sync(0xffffffffu, a1r0, o);
            a0r1 += __shfl_xor_sync(0xffffffffu, a0r1, o);
            a1r1 += __shfl_xor_sync(0xffffffffu, a1r1, o);
        }
        if (lane == 0 && r0 < rowEnd) {
            float a0 = leaky1(a0r0), a1 = leaky1(a1r0);
            float m = fmaxf(a0, a1);
            float e0 = expf(a0 - m), e1 = expf(a1 - m);
            float inv = 1.0f / (e0 + e1);
            out[(size_t)r0 * 2 + 0] = e0 * inv;
            out[(size_t)r0 * 2 + 1] = e1 * inv;
        }
        if (lane == 1 && r1 < rowEnd) {
            float a0 = leaky1(a0r1), a1 = leaky1(a1r1);
            float m = fmaxf(a0, a1);
            float e0 = expf(a0 - m), e1 = expf(a1 - m);
            float inv = 1.0f / (e0 + e1);
            out[(size_t)r1 * 2 + 0] = e0 * inv;
            out[(size_t)r1 * 2 + 1] = e1 * inv;
        }
    }
}

// ---------------- launch ------------------------------------------------------
extern "C" void kernel_launch(void* const* d_in, const int* in_sizes, int n_in,
                              void* d_out, int out_size) {
    const float* x    = (const float*)d_in[0];
    const void*  ei   = d_in[1];
    const float* Wg0  = (const float*)d_in[2];
    const float* Wg1  = (const float*)d_in[3];
    const float* Wg2  = (const float*)d_in[4];
    const float* Wfc1 = (const float*)d_in[5];
    const float* Wfc2 = (const float*)d_in[6];
    float* out = (float*)d_out;

    int N = in_sizes[0] / D;
    int E = in_sizes[1] / 2;

    float *p_ha, *p_hb, *p_x;
    int* p_degi;
    cudaGetSymbolAddress((void**)&p_ha, g_ha);
    cudaGetSymbolAddress((void**)&p_hb, g_hb);
    cudaGetSymbolAddress((void**)&p_x, g_x);
    cudaGetSymbolAddress((void**)&p_degi, g_degi);

    int smem_g = D * 128 * 4;              // 64 KB
    int smem_fc = (D * 256 + 512) * 4;     // ~132 KB
    cudaFuncSetAttribute(gemm128_k,
                         cudaFuncAttributeMaxDynamicSharedMemorySize, smem_g);
    cudaFuncSetAttribute(fc_fused_k,
                         cudaFuncAttributeMaxDynamicSharedMemorySize, smem_fc);

    // Side stream + event pool (created on first, uncaptured, correctness
    // call; reused under graph capture).
    static cudaStream_t s2 = nullptr;
    static cudaEvent_t evp[16];
    if (s2 == nullptr) {
        cudaStreamCreateWithFlags(&s2, cudaStreamNonBlocking);
        for (int i = 0; i < 16; i++)
            cudaEventCreateWithFlags(&evp[i], cudaEventDisableTiming);
    }
    int ein = 0;

    int tpb = 256;
    int gE = (E + tpb - 1) / tpb;
    int gN = (N + tpb - 1) / tpb;
    int nb = (N + 1023) / 1024;

    // ---- fork: CSR build on s2, gemm0 on main stream ----
    cudaEventRecord(evp[ein], 0);
    cudaStreamWaitEvent(s2, evp[ein], 0);
    ein++;

    cudaMemsetAsync(p_degi, 0, (size_t)N * sizeof(int), s2);
    detect_k<<<1, 32, 0, s2>>>((const unsigned int*)ei, E);
    count_k<<<gE, tpb, 0, s2>>>(ei, E);
    scan1_k<<<nb, 1024, 0, s2>>>(N);
    scan2_k<<<1, 64, 0, s2>>>(nb);
    scan3_k<<<gN, tpb, 0, s2>>>(N, E);
    fill_k<<<gE, tpb, 0, s2>>>(ei, E);

    gemm128_k<<<(N + 63) / 64, tpb, smem_g>>>(x, Wg0, p_ha, 0, N);
    cudaEventRecord(evp[ein], 0);          // Ha ready
    cudaStreamWaitEvent(s2, evp[ein], 0);  // s2: CSR done (in-order) + Ha
    ein++;

    // ---- pipelined layers: gathers (chunked, s2) feed gemm/fc chunks (main)
    // Chunk boundaries: multiples of 192 (lcm of 64-row gemm & 96-row fc blocks)
    int chunk = ((N + 2) / 3 + 191) / 192 * 192;
    int cb[4];
    cb[0] = 0;
    cb[1] = chunk < N ? chunk : N;
    cb[2] = 2 * chunk < N ? 2 * chunk : N;
    cb[3] = N;

    const float* WgL[2] = {Wg1, Wg2};
    float* Hbuf[2] = {p_ha, p_hb};
    int cur = 0;  // gather reads Hbuf[cur]; gemm writes Hbuf[1-cur]

    for (int l = 0; l < 3; l++) {
        cudaEvent_t eg[3];
        for (int c = 0; c < 3; c++) {
            int rb = cb[c], re = cb[c + 1];
            if (re > rb)
                gather_k<<<(re - rb + 7) / 8, tpb, 0, s2>>>(Hbuf[cur], p_x,
                                                            rb, re);
            cudaEventRecord(evp[ein], s2);
            eg[c] = evp[ein];
            ein++;
        }
        for (int c = 0; c < 3; c++) {
            int rb = cb[c], re = cb[c + 1];
            cudaStreamWaitEvent(0, eg[c], 0);
            if (re <= rb) continue;
            if (l < 2)
                gemm128_k<<<(re - rb + 63) / 64, tpb, smem_g>>>(
                    p_x, WgL[l], Hbuf[1 - cur], rb, re);
            else
                fc_fused_k<<<(re - rb + 95) / 96, 768, smem_fc>>>(
                    p_x, Wfc1, Wfc2, out, rb, re);
        }
        if (l < 2) {
            cudaEventRecord(evp[ein], 0);          // gemm_l fully done
            cudaStreamWaitEvent(s2, evp[ein], 0);  // next gathers need full H
            ein++;
            cur = 1 - cur;
        }
    }
}

// round 15
// speedup vs baseline: 1.1328x; 1.1328x over previous
#include <cuda_runtime.h>
#include <math.h>

#define NMAX 50000
#define EMAX 800000
#define D 128
#define NB_SCAN ((NMAX + 1023) / 1024)

// ---------------- scratch (device globals; no allocation allowed) ----------
__device__ int    g_is64;
__device__ int    g_degi[NMAX];
__device__ int    g_off[NMAX + 1];
__device__ int    g_cur[NMAX];
__device__ int    g_bsum[NB_SCAN];
__device__ int    g_bpre[NB_SCAN];
__device__ float  g_dinv[NMAX];
__device__ float2 g_emeta[EMAX];   // {src (bitcast int), norm}
__device__ float  g_h[NMAX * D];
__device__ float  g_x[NMAX * D];

// ---------------- f32x2 helpers (Blackwell packed fp32) ---------------------
__device__ __forceinline__ unsigned long long pk2(float lo, float hi) {
    unsigned long long d;
    asm("mov.b64 %0, {%1, %2};" : "=l"(d) : "f"(lo), "f"(hi));
    return d;
}
__device__ __forceinline__ float2 upk2(unsigned long long v) {
    float2 r;
    asm("mov.b64 {%0, %1}, %2;" : "=f"(r.x), "=f"(r.y) : "l"(v));
    return r;
}
__device__ __forceinline__ unsigned long long fma2(unsigned long long a,
                                                   unsigned long long b,
                                                   unsigned long long c) {
    unsigned long long d;
    asm("fma.rn.f32x2 %0, %1, %2, %3;" : "=l"(d) : "l"(a), "l"(b), "l"(c));
    return d;
}

__device__ __forceinline__ float leaky1(float v) {
    return v >= 0.0f ? v : 0.01f * v;
}

// ---------------- edge-index width detection -------------------------------
__global__ void detect_k(const unsigned int* __restrict__ w, int E) {
    __shared__ int nz;
    if (threadIdx.x == 0) nz = 0;
    __syncthreads();
    int n = E < 1024 ? E : 1024;
    for (int i = threadIdx.x; i < n; i += 32)
        if (w[2 * i + 1] != 0u) atomicAdd(&nz, 1);
    __syncthreads();
    if (threadIdx.x == 0) g_is64 = (nz == 0) ? 1 : 0;
}

// ---------------- degree histogram ------------------------------------------
__global__ void count_k(const void* __restrict__ ei, int E) {
    int e = blockIdx.x * blockDim.x + threadIdx.x;
    if (e >= E) return;
    int dst;
    if (g_is64) dst = (int)((const unsigned int*)ei)[2 * (E + e)];
    else        dst = ((const int*)ei)[E + e];
    atomicAdd(&g_degi[dst], 1);
}

// ---------------- scan phase 1 (+ dinv fused) --------------------------------
__global__ void scan1_k(int N) {
    __shared__ int sh[1024];
    int t = threadIdx.x;
    int i = blockIdx.x * 1024 + t;
    int v = (i < N) ? g_degi[i] : 0;
    if (i < N) g_dinv[i] = rsqrtf((float)v + 1.0f);  // + self loop
    sh[t] = v;
    __syncthreads();
#pragma unroll
    for (int off = 1; off < 1024; off <<= 1) {
        int u = (t >= off) ? sh[t - off] : 0;
        __syncthreads();
        sh[t] += u;
        __syncthreads();
    }
    if (i < N) g_off[i] = sh[t] - v;            // block-local exclusive
    if (t == 1023) g_bsum[blockIdx.x] = sh[1023];
}

// 64-thread Hillis-Steele over <=64 block sums
__global__ void scan2_k(int nb) {
    __shared__ int sh[64];
    int t = threadIdx.x;
    int v = (t < nb) ? g_bsum[t] : 0;
    sh[t] = v;
    __syncthreads();
#pragma unroll
    for (int off = 1; off < 64; off <<= 1) {
        int u = (t >= off) ? sh[t - off] : 0;
        __syncthreads();
        sh[t] += u;
        __syncthreads();
    }
    if (t < nb) g_bpre[t] = sh[t] - v;          // exclusive
}

__global__ void scan3_k(int N, int E) {
    int i = blockIdx.x * blockDim.x + threadIdx.x;
    if (i < N) {
        int v = g_off[i] + g_bpre[i >> 10];
        g_off[i] = v;
        g_cur[i] = v;
    }
    if (i == 0) g_off[N] = E;   // sum of degrees == E
}

// ---------------- CSR fill: bucket edges by dst -----------------------------
__global__ void fill_k(const void* __restrict__ ei, int E) {
    int e = blockIdx.x * blockDim.x + threadIdx.x;
    if (e >= E) return;
    int src, dst;
    if (g_is64) {
        src = (int)((const unsigned int*)ei)[2 * e];
        dst = (int)((const unsigned int*)ei)[2 * (E + e)];
    } else {
        src = ((const int*)ei)[e];
        dst = ((const int*)ei)[E + e];
    }
    float norm = g_dinv[src] * g_dinv[dst];
    int p = atomicAdd(&g_cur[dst], 1);
    g_emeta[p] = make_float2(__int_as_float(src), norm);
}

// ---------------- GEMM: H = X @ W  (K = 128, NOUT = 128), packed f32x2 ------
__global__ void gemm128_k(const float* __restrict__ X,
                          const float* __restrict__ W,
                          float* __restrict__ H, int N) {
    extern __shared__ float4 Ws4[];  // D*128 floats
    const float4* W4 = (const float4*)W;
    for (int i = threadIdx.x; i < D * 128 / 4; i += blockDim.x) Ws4[i] = W4[i];
    __syncthreads();

    constexpr int P = 4;  // row pairs (8 rows per warp)
    int lane = threadIdx.x & 31;
    int warp_g = blockIdx.x * (blockDim.x >> 5) + (threadIdx.x >> 5);
    int row0 = warp_g * 8;
    if (row0 >= N) return;

    unsigned long long xp[P][4];
#pragma unroll
    for (int p = 0; p < P; p++) {
        int r0 = row0 + 2 * p, r1 = r0 + 1;
        float4 a = (r0 < N) ? ((const float4*)(X + (size_t)r0 * D))[lane]
                            : make_float4(0.f, 0.f, 0.f, 0.f);
        float4 b = (r1 < N) ? ((const float4*)(X + (size_t)r1 * D))[lane]
                            : make_float4(0.f, 0.f, 0.f, 0.f);
        xp[p][0] = pk2(a.x, b.x);
        xp[p][1] = pk2(a.y, b.y);
        xp[p][2] = pk2(a.z, b.z);
        xp[p][3] = pk2(a.w, b.w);
    }

    unsigned long long acc[P][4];
#pragma unroll
    for (int p = 0; p < P; p++)
#pragma unroll
        for (int c = 0; c < 4; c++) acc[p][c] = 0ull;

    for (int sl = 0; sl < 32; ++sl) {
#pragma unroll
        for (int kl = 0; kl < 4; kl++) {
            unsigned long long xs[P];
#pragma unroll
            for (int p = 0; p < P; p++)
                xs[p] = __shfl_sync(0xffffffffu, xp[p][kl], sl);
            int k = sl * 4 + kl;
            float4 wv = Ws4[(size_t)k * 32 + lane];
            unsigned long long w0 = pk2(wv.x, wv.x);
            unsigned long long w1 = pk2(wv.y, wv.y);
            unsigned long long w2 = pk2(wv.z, wv.z);
            unsigned long long w3 = pk2(wv.w, wv.w);
#pragma unroll
            for (int p = 0; p < P; p++) {
                acc[p][0] = fma2(xs[p], w0, acc[p][0]);
                acc[p][1] = fma2(xs[p], w1, acc[p][1]);
                acc[p][2] = fma2(xs[p], w2, acc[p][2]);
                acc[p][3] = fma2(xs[p], w3, acc[p][3]);
            }
        }
    }

#pragma unroll
    for (int p = 0; p < P; p++) {
        int r0 = row0 + 2 * p, r1 = r0 + 1;
        float2 c0 = upk2(acc[p][0]);
        float2 c1 = upk2(acc[p][1]);
        float2 c2 = upk2(acc[p][2]);
        float2 c3 = upk2(acc[p][3]);
        if (r0 < N)
            ((float4*)(H + (size_t)r0 * 128))[lane] =
                make_float4(c0.x, c1.x, c2.x, c3.x);
        if (r1 < N)
            ((float4*)(H + (size_t)r1 * 128))[lane] =
                make_float4(c0.y, c1.y, c2.y, c3.y);
    }
}

// ---------------- gather: X[i] = leaky(dinv_i^2*H[i] + sum norm*H[src]) -----
// One warp per node; launched at 512 threads (16 warps/block).
__global__ void gather_k(const float* __restrict__ H, float* __restrict__ X,
                         int N) {
    int lane = threadIdx.x & 31;
    int node = blockIdx.x * (blockDim.x >> 5) + (threadIdx.x >> 5);
    if (node >= N) return;
    int beg = g_off[node], end = g_off[node + 1];
    float s = g_dinv[node];
    float w0 = s * s;
    float4 acc = ((const float4*)(H + (size_t)node * D))[lane];
    acc.x *= w0; acc.y *= w0; acc.z *= w0; acc.w *= w0;

    int j = beg;
    for (; j + 1 < end; j += 2) {
        float2 m0 = g_emeta[j];
        float2 m1 = g_emeta[j + 1];
        int s0 = __float_as_int(m0.x);
        int s1 = __float_as_int(m1.x);
        float4 v0 = ((const float4*)(H + (size_t)s0 * D))[lane];
        float4 v1 = ((const float4*)(H + (size_t)s1 * D))[lane];
        acc.x += m0.y * v0.x + m1.y * v1.x;
        acc.y += m0.y * v0.y + m1.y * v1.y;
        acc.z += m0.y * v0.z + m1.y * v1.z;
        acc.w += m0.y * v0.w + m1.y * v1.w;
    }
    if (j < end) {
        float2 m = g_emeta[j];
        int src = __float_as_int(m.x);
        float w = m.y;
        float4 v = ((const float4*)(H + (size_t)src * D))[lane];
        acc.x += w * v.x; acc.y += w * v.y;
        acc.z += w * v.z; acc.w += w * v.w;
    }
    acc.x = leaky1(acc.x); acc.y = leaky1(acc.y);
    acc.z = leaky1(acc.z); acc.w = leaky1(acc.w);
    ((float4*)(X + (size_t)node * D))[lane] = acc;
}

// ---------------- fused fc1 (128->256) + leaky + fc2 (256->2) + softmax -----
// Launch with 768 threads (24 warps, 4 rows/warp = 96 rows/block).
__global__ void __launch_bounds__(768, 1)
fc_fused_k(const float* __restrict__ X,
           const float* __restrict__ W1,
           const float* __restrict__ W2,
           float* __restrict__ out, int N) {
    extern __shared__ float4 Ws4[];  // D*256 floats for W1, then 512 for W2
    float4* W2s4 = Ws4 + D * 256 / 4;
    const float4* W14 = (const float4*)W1;
    for (int i = threadIdx.x; i < D * 256 / 4; i += blockDim.x) Ws4[i] = W14[i];
    float* W2s = (float*)W2s4;
    for (int i = threadIdx.x; i < 256; i += blockDim.x) {
        W2s[i]       = W2[2 * i];
        W2s[256 + i] = W2[2 * i + 1];
    }
    __syncthreads();

    constexpr int P = 2;  // row pairs (4 rows per warp)
    int lane = threadIdx.x & 31;
    int warp_g = blockIdx.x * (blockDim.x >> 5) + (threadIdx.x >> 5);
    int row0 = warp_g * 4;
    if (row0 >= N) return;

    unsigned long long xp[P][4];
#pragma unroll
    for (int p = 0; p < P; p++) {
        int r0 = row0 + 2 * p, r1 = r0 + 1;
        float4 a = (r0 < N) ? ((const float4*)(X + (size_t)r0 * D))[lane]
                            : make_float4(0.f, 0.f, 0.f, 0.f);
        float4 b = (r1 < N) ? ((const float4*)(X + (size_t)r1 * D))[lane]
                            : make_float4(0.f, 0.f, 0.f, 0.f);
        xp[p][0] = pk2(a.x, b.x);
        xp[p][1] = pk2(a.y, b.y);
        xp[p][2] = pk2(a.z, b.z);
        xp[p][3] = pk2(a.w, b.w);
    }

    unsigned long long acc[P][8];
#pragma unroll
    for (int p = 0; p < P; p++)
#pragma unroll
        for (int c = 0; c < 8; c++) acc[p][c] = 0ull;

    for (int sl = 0; sl < 32; ++sl) {
#pragma unroll
        for (int kl = 0; kl < 4; kl++) {
            unsigned long long xs[P];
#pragma unroll
            for (int p = 0; p < P; p++)
                xs[p] = __shfl_sync(0xffffffffu, xp[p][kl], sl);
            int k = sl * 4 + kl;
#pragma unroll
            for (int c = 0; c < 2; c++) {
                float4 wv = Ws4[(size_t)k * 64 + lane + 32 * c];
                unsigned long long w0 = pk2(wv.x, wv.x);
                unsigned long long w1 = pk2(wv.y, wv.y);
                unsigned long long w2 = pk2(wv.z, wv.z);
                unsigned long long w3 = pk2(wv.w, wv.w);
#pragma unroll
                for (int p = 0; p < P; p++) {
                    acc[p][4 * c + 0] = fma2(xs[p], w0, acc[p][4 * c + 0]);
                    acc[p][4 * c + 1] = fma2(xs[p], w1, acc[p][4 * c + 1]);
                    acc[p][4 * c + 2] = fma2(xs[p], w2, acc[p][4 * c + 2]);
                    acc[p][4 * c + 3] = fma2(xs[p], w3, acc[p][4 * c + 3]);
                }
            }
        }
    }

    const float4* w0s4 = (const float4*)W2s;
    const float4* w1s4 = (const float4*)(W2s + 256);
#pragma unroll
    for (int p = 0; p < P; p++) {
        int r0 = row0 + 2 * p, r1 = r0 + 1;
        float a0r0 = 0.f, a1r0 = 0.f, a0r1 = 0.f, a1r1 = 0.f;
#pragma unroll
        for (int c = 0; c < 2; c++) {
            float2 c0 = upk2(acc[p][4 * c + 0]);
            float2 c1 = upk2(acc[p][4 * c + 1]);
            float2 c2 = upk2(acc[p][4 * c + 2]);
            float2 c3 = upk2(acc[p][4 * c + 3]);
            float4 y0 = make_float4(leaky1(c0.x), leaky1(c1.x),
                                    leaky1(c2.x), leaky1(c3.x));
            float4 y1 = make_float4(leaky1(c0.y), leaky1(c1.y),
                                    leaky1(c2.y), leaky1(c3.y));
            float4 u0 = w0s4[lane + 32 * c];
            float4 u1 = w1s4[lane + 32 * c];
            a0r0 += y0.x * u0.x + y0.y * u0.y + y0.z * u0.z + y0.w * u0.w;
            a1r0 += y0.x * u1.x + y0.y * u1.y + y0.z * u1.z + y0.w * u1.w;
            a0r1 += y1.x * u0.x + y1.y * u0.y + y1.z * u0.z + y1.w * u0.w;
            a1r1 += y1.x * u1.x + y1.y * u1.y + y1.z * u1.z + y1.w * u1.w;
        }
#pragma unroll
        for (int o = 16; o; o >>= 1) {
            a0r0 += __shfl_xor_sync(0xffffffffu, a0r0, o);
            a1r0 += __shfl_xor_sync(0xffffffffu, a1r0, o);
            a0r1 += __shfl_xor_sync(0xffffffffu, a0r1, o);
            a1r1 += __shfl_xor_sync(0xffffffffu, a1r1, o);
        }
        if (lane == 0 && r0 < N) {
            float a0 = leaky1(a0r0), a1 = leaky1(a1r0);
            float m = fmaxf(a0, a1);
            float e0 = expf(a0 - m), e1 = expf(a1 - m);
            float inv = 1.0f / (e0 + e1);
            out[(size_t)r0 * 2 + 0] = e0 * inv;
            out[(size_t)r0 * 2 + 1] = e1 * inv;
        }
        if (lane == 1 && r1 < N) {
            float a0 = leaky1(a0r1), a1 = leaky1(a1r1);
            float m = fmaxf(a0, a1);
            float e0 = expf(a0 - m), e1 = expf(a1 - m);
            float inv = 1.0f / (e0 + e1);
            out[(size_t)r1 * 2 + 0] = e0 * inv;
            out[(size_t)r1 * 2 + 1] = e1 * inv;
        }
    }
}

// ---------------- launch ------------------------------------------------------
extern "C" void kernel_launch(void* const* d_in, const int* in_sizes, int n_in,
                              void* d_out, int out_size) {
    const float* x    = (const float*)d_in[0];
    const void*  ei   = d_in[1];
    const float* Wg0  = (const float*)d_in[2];
    const float* Wg1  = (const float*)d_in[3];
    const float* Wg2  = (const float*)d_in[4];
    const float* Wfc1 = (const float*)d_in[5];
    const float* Wfc2 = (const float*)d_in[6];
    float* out = (float*)d_out;

    int N = in_sizes[0] / D;
    int E = in_sizes[1] / 2;

    float *p_h, *p_x;
    int* p_degi;
    cudaGetSymbolAddress((void**)&p_h, g_h);
    cudaGetSymbolAddress((void**)&p_x, g_x);
    cudaGetSymbolAddress((void**)&p_degi, g_degi);

    int smem_g = D * 128 * 4;              // 64 KB
    int smem_fc = (D * 256 + 512) * 4;     // ~132 KB
    cudaFuncSetAttribute(gemm128_k,
                         cudaFuncAttributeMaxDynamicSharedMemorySize, smem_g);
    cudaFuncSetAttribute(fc_fused_k,
                         cudaFuncAttributeMaxDynamicSharedMemorySize, smem_fc);

    // Side stream + events for CSR/gemm0 overlap (created on first,
    // uncaptured, correctness call; reused under graph capture).
    static cudaStream_t s2 = nullptr;
    static cudaEvent_t ev_fork = nullptr, ev_join = nullptr;
    if (s2 == nullptr) {
        cudaStreamCreateWithFlags(&s2, cudaStreamNonBlocking);
        cudaEventCreateWithFlags(&ev_fork, cudaEventDisableTiming);
        cudaEventCreateWithFlags(&ev_join, cudaEventDisableTiming);
    }

    int tpb = 256;
    int gE = (E + tpb - 1) / tpb;
    int gN = (N + tpb - 1) / tpb;
    int nb = (N + 1023) / 1024;

    // ---- fork: CSR build on side stream, gemm0 on main stream ----
    cudaEventRecord(ev_fork, 0);
    cudaStreamWaitEvent(s2, ev_fork, 0);

    cudaMemsetAsync(p_degi, 0, (size_t)N * sizeof(int), s2);
    detect_k<<<1, 32, 0, s2>>>((const unsigned int*)ei, E);
    count_k<<<gE, tpb, 0, s2>>>(ei, E);
    scan1_k<<<nb, 1024, 0, s2>>>(N);
    scan2_k<<<1, 64, 0, s2>>>(nb);
    scan3_k<<<gN, tpb, 0, s2>>>(N, E);
    fill_k<<<gE, tpb, 0, s2>>>(ei, E);
    cudaEventRecord(ev_join, s2);

    int gb128 = (N + 63) / 64;   // 8 warps * 8 rows per block
    int gga   = (N + 15) / 16;   // 1 warp per node, 16 warps/block (512 thr)
    gemm128_k<<<gb128, tpb, smem_g>>>(x, Wg0, p_h, N);

    // ---- join: gather needs both CSR and gemm0 ----
    cudaStreamWaitEvent(0, ev_join, 0);

    gather_k<<<gga, 512>>>(p_h, p_x, N);
    gemm128_k<<<gb128, tpb, smem_g>>>(p_x, Wg1, p_h, N);
    gather_k<<<gga, 512>>>(p_h, p_x, N);
    gemm128_k<<<gb128, tpb, smem_g>>>(p_x, Wg2, p_h, N);
    gather_k<<<gga, 512>>>(p_h, p_x, N);

    // ---- fused fc1 + fc2 + softmax: 768 threads, 24 warps * 4 rows = 96 ----
    int gbfc = (N + 95) / 96;
    fc_fused_k<<<gbfc, 768, smem_fc>>>(p_x, Wfc1, Wfc2, out, N);
}

// round 17
// speedup vs baseline: 1.1458x; 1.0114x over previous
#include <cuda_runtime.h>
#include <math.h>

#define NMAX 50000
#define EMAX 800000
#define D 128
#define NB_SCAN ((NMAX + 1023) / 1024)

// ---------------- scratch (device globals; no allocation allowed) ----------
__device__ int    g_is64;
__device__ int    g_degi[NMAX];
__device__ int    g_off[NMAX + 1];
__device__ int    g_cur[NMAX];
__device__ int    g_bsum[NB_SCAN];
__device__ int    g_bpre[NB_SCAN];
__device__ float  g_dinv[NMAX];
__device__ float2 g_emeta[EMAX];   // {src (bitcast int), norm}
__device__ float  g_h[NMAX * D];
__device__ float  g_x[NMAX * D];

// ---------------- f32x2 helpers (Blackwell packed fp32) ---------------------
__device__ __forceinline__ unsigned long long pk2(float lo, float hi) {
    unsigned long long d;
    asm("mov.b64 %0, {%1, %2};" : "=l"(d) : "f"(lo), "f"(hi));
    return d;
}
__device__ __forceinline__ float2 upk2(unsigned long long v) {
    float2 r;
    asm("mov.b64 {%0, %1}, %2;" : "=f"(r.x), "=f"(r.y) : "l"(v));
    return r;
}
__device__ __forceinline__ unsigned long long fma2(unsigned long long a,
                                                   unsigned long long b,
                                                   unsigned long long c) {
    unsigned long long d;
    asm("fma.rn.f32x2 %0, %1, %2, %3;" : "=l"(d) : "l"(a), "l"(b), "l"(c));
    return d;
}

__device__ __forceinline__ float leaky1(float v) {
    return v >= 0.0f ? v : 0.01f * v;
}

// ---------------- edge-index width detection -------------------------------
__global__ void detect_k(const unsigned int* __restrict__ w, int E) {
    __shared__ int nz;
    if (threadIdx.x == 0) nz = 0;
    __syncthreads();
    int n = E < 1024 ? E : 1024;
    for (int i = threadIdx.x; i < n; i += 32)
        if (w[2 * i + 1] != 0u) atomicAdd(&nz, 1);
    __syncthreads();
    if (threadIdx.x == 0) g_is64 = (nz == 0) ? 1 : 0;
}

// ---------------- degree histogram ------------------------------------------
__global__ void count_k(const void* __restrict__ ei, int E) {
    int e = blockIdx.x * blockDim.x + threadIdx.x;
    if (e >= E) return;
    int dst;
    if (g_is64) dst = (int)((const unsigned int*)ei)[2 * (E + e)];
    else        dst = ((const int*)ei)[E + e];
    atomicAdd(&g_degi[dst], 1);
}

// ---------------- scan phase 1 (+ dinv fused) --------------------------------
__global__ void scan1_k(int N) {
    __shared__ int sh[1024];
    int t = threadIdx.x;
    int i = blockIdx.x * 1024 + t;
    int v = (i < N) ? g_degi[i] : 0;
    if (i < N) g_dinv[i] = rsqrtf((float)v + 1.0f);  // + self loop
    sh[t] = v;
    __syncthreads();
#pragma unroll
    for (int off = 1; off < 1024; off <<= 1) {
        int u = (t >= off) ? sh[t - off] : 0;
        __syncthreads();
        sh[t] += u;
        __syncthreads();
    }
    if (i < N) g_off[i] = sh[t] - v;            // block-local exclusive
    if (t == 1023) g_bsum[blockIdx.x] = sh[1023];
}

// 64-thread Hillis-Steele over <=64 block sums
__global__ void scan2_k(int nb) {
    __shared__ int sh[64];
    int t = threadIdx.x;
    int v = (t < nb) ? g_bsum[t] : 0;
    sh[t] = v;
    __syncthreads();
#pragma unroll
    for (int off = 1; off < 64; off <<= 1) {
        int u = (t >= off) ? sh[t - off] : 0;
        __syncthreads();
        sh[t] += u;
        __syncthreads();
    }
    if (t < nb) g_bpre[t] = sh[t] - v;          // exclusive
}

__global__ void scan3_k(int N, int E) {
    int i = blockIdx.x * blockDim.x + threadIdx.x;
    if (i < N) {
        int v = g_off[i] + g_bpre[i >> 10];
        g_off[i] = v;
        g_cur[i] = v;
    }
    if (i == 0) g_off[N] = E;   // sum of degrees == E
}

// ---------------- CSR fill: bucket edges by dst -----------------------------
__global__ void fill_k(const void* __restrict__ ei, int E) {
    int e = blockIdx.x * blockDim.x + threadIdx.x;
    if (e >= E) return;
    int src, dst;
    if (g_is64) {
        src = (int)((const unsigned int*)ei)[2 * e];
        dst = (int)((const unsigned int*)ei)[2 * (E + e)];
    } else {
        src = ((const int*)ei)[e];
        dst = ((const int*)ei)[E + e];
    }
    float norm = g_dinv[src] * g_dinv[dst];
    int p = atomicAdd(&g_cur[dst], 1);
    g_emeta[p] = make_float2(__int_as_float(src), norm);
}

// ---------------- GEMM: H = X @ W  (K = 128, NOUT = 128), packed f32x2 ------
__global__ void gemm128_k(const float* __restrict__ X,
                          const float* __restrict__ W,
                          float* __restrict__ H, int N) {
    extern __shared__ float4 Ws4[];  // D*128 floats
    const float4* W4 = (const float4*)W;
    for (int i = threadIdx.x; i < D * 128 / 4; i += blockDim.x) Ws4[i] = W4[i];
    __syncthreads();

    constexpr int P = 4;  // row pairs (8 rows per warp)
    int lane = threadIdx.x & 31;
    int warp_g = blockIdx.x * (blockDim.x >> 5) + (threadIdx.x >> 5);
    int row0 = warp_g * 8;
    if (row0 >= N) return;

    unsigned long long xp[P][4];
#pragma unroll
    for (int p = 0; p < P; p++) {
        int r0 = row0 + 2 * p, r1 = r0 + 1;
        float4 a = (r0 < N) ? ((const float4*)(X + (size_t)r0 * D))[lane]
                            : make_float4(0.f, 0.f, 0.f, 0.f);
        float4 b = (r1 < N) ? ((const float4*)(X + (size_t)r1 * D))[lane]
                            : make_float4(0.f, 0.f, 0.f, 0.f);
        xp[p][0] = pk2(a.x, b.x);
        xp[p][1] = pk2(a.y, b.y);
        xp[p][2] = pk2(a.z, b.z);
        xp[p][3] = pk2(a.w, b.w);
    }

    unsigned long long acc[P][4];
#pragma unroll
    for (int p = 0; p < P; p++)
#pragma unroll
        for (int c = 0; c < 4; c++) acc[p][c] = 0ull;

    for (int sl = 0; sl < 32; ++sl) {
#pragma unroll
        for (int kl = 0; kl < 4; kl++) {
            unsigned long long xs[P];
#pragma unroll
            for (int p = 0; p < P; p++)
                xs[p] = __shfl_sync(0xffffffffu, xp[p][kl], sl);
            int k = sl * 4 + kl;
            float4 wv = Ws4[(size_t)k * 32 + lane];
            unsigned long long w0 = pk2(wv.x, wv.x);
            unsigned long long w1 = pk2(wv.y, wv.y);
            unsigned long long w2 = pk2(wv.z, wv.z);
            unsigned long long w3 = pk2(wv.w, wv.w);
#pragma unroll
            for (int p = 0; p < P; p++) {
                acc[p][0] = fma2(xs[p], w0, acc[p][0]);
                acc[p][1] = fma2(xs[p], w1, acc[p][1]);
                acc[p][2] = fma2(xs[p], w2, acc[p][2]);
                acc[p][3] = fma2(xs[p], w3, acc[p][3]);
            }
        }
    }

#pragma unroll
    for (int p = 0; p < P; p++) {
        int r0 = row0 + 2 * p, r1 = r0 + 1;
        float2 c0 = upk2(acc[p][0]);
        float2 c1 = upk2(acc[p][1]);
        float2 c2 = upk2(acc[p][2]);
        float2 c3 = upk2(acc[p][3]);
        if (r0 < N)
            ((float4*)(H + (size_t)r0 * 128))[lane] =
                make_float4(c0.x, c1.x, c2.x, c3.x);
        if (r1 < N)
            ((float4*)(H + (size_t)r1 * 128))[lane] =
                make_float4(c0.y, c1.y, c2.y, c3.y);
    }
}

// ---------------- gather: X[i] = leaky(dinv_i^2*H[i] + sum norm*H[src]) -----
// One warp per node; 256 threads (8 warps/block) — champion config.
__global__ void gather_k(const float* __restrict__ H, float* __restrict__ X,
                         int N) {
    int lane = threadIdx.x & 31;
    int node = blockIdx.x * (blockDim.x >> 5) + (threadIdx.x >> 5);
    if (node >= N) return;
    int beg = g_off[node], end = g_off[node + 1];
    float s = g_dinv[node];
    float w0 = s * s;
    float4 acc = ((const float4*)(H + (size_t)node * D))[lane];
    acc.x *= w0; acc.y *= w0; acc.z *= w0; acc.w *= w0;

    int j = beg;
    for (; j + 1 < end; j += 2) {
        float2 m0 = g_emeta[j];
        float2 m1 = g_emeta[j + 1];
        int s0 = __float_as_int(m0.x);
        int s1 = __float_as_int(m1.x);
        float4 v0 = ((const float4*)(H + (size_t)s0 * D))[lane];
        float4 v1 = ((const float4*)(H + (size_t)s1 * D))[lane];
        acc.x += m0.y * v0.x + m1.y * v1.x;
        acc.y += m0.y * v0.y + m1.y * v1.y;
        acc.z += m0.y * v0.z + m1.y * v1.z;
        acc.w += m0.y * v0.w + m1.y * v1.w;
    }
    if (j < end) {
        float2 m = g_emeta[j];
        int src = __float_as_int(m.x);
        float w = m.y;
        float4 v = ((const float4*)(H + (size_t)src * D))[lane];
        acc.x += w * v.x; acc.y += w * v.y;
        acc.z += w * v.z; acc.w += w * v.w;
    }
    acc.x = leaky1(acc.x); acc.y = leaky1(acc.y);
    acc.z = leaky1(acc.z); acc.w = leaky1(acc.w);
    ((float4*)(X + (size_t)node * D))[lane] = acc;
}

// ---------------- fused fc1 (128->256) + leaky + fc2 (256->2) + softmax -----
// Launch with 768 threads (24 warps, 4 rows/warp = 96 rows/block).
__global__ void __launch_bounds__(768, 1)
fc_fused_k(const float* __restrict__ X,
           const float* __restrict__ W1,
           const float* __restrict__ W2,
           float* __restrict__ out, int N) {
    extern __shared__ float4 Ws4[];  // D*256 floats for W1, then 512 for W2
    float4* W2s4 = Ws4 + D * 256 / 4;
    const float4* W14 = (const float4*)W1;
    for (int i = threadIdx.x; i < D * 256 / 4; i += blockDim.x) Ws4[i] = W14[i];
    float* W2s = (float*)W2s4;
    for (int i = threadIdx.x; i < 256; i += blockDim.x) {
        W2s[i]       = W2[2 * i];
        W2s[256 + i] = W2[2 * i + 1];
    }
    __syncthreads();

    constexpr int P = 2;  // row pairs (4 rows per warp)
    int lane = threadIdx.x & 31;
    int warp_g = blockIdx.x * (blockDim.x >> 5) + (threadIdx.x >> 5);
    int row0 = warp_g * 4;
    if (row0 >= N) return;

    unsigned long long xp[P][4];
#pragma unroll
    for (int p = 0; p < P; p++) {
        int r0 = row0 + 2 * p, r1 = r0 + 1;
        float4 a = (r0 < N) ? ((const float4*)(X + (size_t)r0 * D))[lane]
                            : make_float4(0.f, 0.f, 0.f, 0.f);
        float4 b = (r1 < N) ? ((const float4*)(X + (size_t)r1 * D))[lane]
                            : make_float4(0.f, 0.f, 0.f, 0.f);
        xp[p][0] = pk2(a.x, b.x);
        xp[p][1] = pk2(a.y, b.y);
        xp[p][2] = pk2(a.z, b.z);
        xp[p][3] = pk2(a.w, b.w);
    }

    unsigned long long acc[P][8];
#pragma unroll
    for (int p = 0; p < P; p++)
#pragma unroll
        for (int c = 0; c < 8; c++) acc[p][c] = 0ull;

    for (int sl = 0; sl < 32; ++sl) {
#pragma unroll
        for (int kl = 0; kl < 4; kl++) {
            unsigned long long xs[P];
#pragma unroll
            for (int p = 0; p < P; p++)
                xs[p] = __shfl_sync(0xffffffffu, xp[p][kl], sl);
            int k = sl * 4 + kl;
#pragma unroll
            for (int c = 0; c < 2; c++) {
                float4 wv = Ws4[(size_t)k * 64 + lane + 32 * c];
                unsigned long long w0 = pk2(wv.x, wv.x);
                unsigned long long w1 = pk2(wv.y, wv.y);
                unsigned long long w2 = pk2(wv.z, wv.z);
                unsigned long long w3 = pk2(wv.w, wv.w);
#pragma unroll
                for (int p = 0; p < P; p++) {
                    acc[p][4 * c + 0] = fma2(xs[p], w0, acc[p][4 * c + 0]);
                    acc[p][4 * c + 1] = fma2(xs[p], w1, acc[p][4 * c + 1]);
                    acc[p][4 * c + 2] = fma2(xs[p], w2, acc[p][4 * c + 2]);
                    acc[p][4 * c + 3] = fma2(xs[p], w3, acc[p][4 * c + 3]);
                }
            }
        }
    }

    const float4* w0s4 = (const float4*)W2s;
    const float4* w1s4 = (const float4*)(W2s + 256);
#pragma unroll
    for (int p = 0; p < P; p++) {
        int r0 = row0 + 2 * p, r1 = r0 + 1;
        float a0r0 = 0.f, a1r0 = 0.f, a0r1 = 0.f, a1r1 = 0.f;
#pragma unroll
        for (int c = 0; c < 2; c++) {
            float2 c0 = upk2(acc[p][4 * c + 0]);
            float2 c1 = upk2(acc[p][4 * c + 1]);
            float2 c2 = upk2(acc[p][4 * c + 2]);
            float2 c3 = upk2(acc[p][4 * c + 3]);
            float4 y0 = make_float4(leaky1(c0.x), leaky1(c1.x),
                                    leaky1(c2.x), leaky1(c3.x));
            float4 y1 = make_float4(leaky1(c0.y), leaky1(c1.y),
                                    leaky1(c2.y), leaky1(c3.y));
            float4 u0 = w0s4[lane + 32 * c];
            float4 u1 = w1s4[lane + 32 * c];
            a0r0 += y0.x * u0.x + y0.y * u0.y + y0.z * u0.z + y0.w * u0.w;
            a1r0 += y0.x * u1.x + y0.y * u1.y + y0.z * u1.z + y0.w * u1.w;
            a0r1 += y1.x * u0.x + y1.y * u0.y + y1.z * u0.z + y1.w * u0.w;
            a1r1 += y1.x * u1.x + y1.y * u1.y + y1.z * u1.z + y1.w * u1.w;
        }
#pragma unroll
        for (int o = 16; o; o >>= 1) {
            a0r0 += __shfl_xor_sync(0xffffffffu, a0r0, o);
            a1r0 += __shfl_xor_sync(0xffffffffu, a1r0, o);
            a0r1 += __shfl_xor_sync(0xffffffffu, a0r1, o);
            a1r1 += __shfl_xor_sync(0xffffffffu, a1r1, o);
        }
        if (lane == 0 && r0 < N) {
            float a0 = leaky1(a0r0), a1 = leaky1(a1r0);
            float m = fmaxf(a0, a1);
            float e0 = expf(a0 - m), e1 = expf(a1 - m);
            float inv = 1.0f / (e0 + e1);
            out[(size_t)r0 * 2 + 0] = e0 * inv;
            out[(size_t)r0 * 2 + 1] = e1 * inv;
        }
        if (lane == 1 && r1 < N) {
            float a0 = leaky1(a0r1), a1 = leaky1(a1r1);
            float m = fmaxf(a0, a1);
            float e0 = expf(a0 - m), e1 = expf(a1 - m);
            float inv = 1.0f / (e0 + e1);
            out[(size_t)r1 * 2 + 0] = e0 * inv;
            out[(size_t)r1 * 2 + 1] = e1 * inv;
        }
    }
}

// ---------------- launch ------------------------------------------------------
extern "C" void kernel_launch(void* const* d_in, const int* in_sizes, int n_in,
                              void* d_out, int out_size) {
    const float* x    = (const float*)d_in[0];
    const void*  ei   = d_in[1];
    const float* Wg0  = (const float*)d_in[2];
    const float* Wg1  = (const float*)d_in[3];
    const float* Wg2  = (const float*)d_in[4];
    const float* Wfc1 = (const float*)d_in[5];
    const float* Wfc2 = (const float*)d_in[6];
    float* out = (float*)d_out;

    int N = in_sizes[0] / D;
    int E = in_sizes[1] / 2;

    float *p_h, *p_x;
    int* p_degi;
    cudaGetSymbolAddress((void**)&p_h, g_h);
    cudaGetSymbolAddress((void**)&p_x, g_x);
    cudaGetSymbolAddress((void**)&p_degi, g_degi);

    int smem_g = D * 128 * 4;              // 64 KB
    int smem_fc = (D * 256 + 512) * 4;     // ~132 KB
    cudaFuncSetAttribute(gemm128_k,
                         cudaFuncAttributeMaxDynamicSharedMemorySize, smem_g);
    cudaFuncSetAttribute(fc_fused_k,
                         cudaFuncAttributeMaxDynamicSharedMemorySize, smem_fc);

    // Side stream + events for CSR/gemm0 overlap (created on first,
    // uncaptured, correctness call; reused under graph capture).
    static cudaStream_t s2 = nullptr;
    static cudaEvent_t ev_fork = nullptr, ev_join = nullptr;
    if (s2 == nullptr) {
        cudaStreamCreateWithFlags(&s2, cudaStreamNonBlocking);
        cudaEventCreateWithFlags(&ev_fork, cudaEventDisableTiming);
        cudaEventCreateWithFlags(&ev_join, cudaEventDisableTiming);
    }

    int tpb = 256;
    int gE = (E + tpb - 1) / tpb;
    int gN = (N + tpb - 1) / tpb;
    int nb = (N + 1023) / 1024;

    // ---- fork: CSR build on side stream, gemm0 on main stream ----
    cudaEventRecord(ev_fork, 0);
    cudaStreamWaitEvent(s2, ev_fork, 0);

    cudaMemsetAsync(p_degi, 0, (size_t)N * sizeof(int), s2);
    detect_k<<<1, 32, 0, s2>>>((const unsigned int*)ei, E);
    count_k<<<gE, tpb, 0, s2>>>(ei, E);
    scan1_k<<<nb, 1024, 0, s2>>>(N);
    scan2_k<<<1, 64, 0, s2>>>(nb);
    scan3_k<<<gN, tpb, 0, s2>>>(N, E);
    fill_k<<<gE, tpb, 0, s2>>>(ei, E);
    cudaEventRecord(ev_join, s2);

    int gb128 = (N + 63) / 64;   // 8 warps * 8 rows per block
    int gga   = (N + 7) / 8;     // 1 warp per node, 8 warps/block (256 thr)
    gemm128_k<<<gb128, tpb, smem_g>>>(x, Wg0, p_h, N);

    // ---- join: gather needs both CSR and gemm0 ----
    cudaStreamWaitEvent(0, ev_join, 0);

    gather_k<<<gga, tpb>>>(p_h, p_x, N);
    gemm128_k<<<gb128, tpb, smem_g>>>(p_x, Wg1, p_h, N);
    gather_k<<<gga, tpb>>>(p_h, p_x, N);
    gemm128_k<<<gb128, tpb, smem_g>>>(p_x, Wg2, p_h, N);
    gather_k<<<gga, tpb>>>(p_h, p_x, N);

    // ---- fused fc1 + fc2 + softmax: 768 threads, 24 warps * 4 rows = 96 ----
    int gbfc = (N + 95) / 96;
    fc_fused_k<<<gbfc, 768, smem_fc>>>(p_x, Wfc1, Wfc2, out, N);
}